// round 4
// baseline (speedup 1.0000x reference)
#include <cuda_runtime.h>
#include <cstdint>

#define NN 100000
#define EE 600000
#define ELN 200000

typedef unsigned long long ull;

// ---- packed f32x2 helpers (FFMA2 — ptxas never emits from C++) ----
__device__ __forceinline__ ull pk2(float x) {
    ull r; unsigned u = __float_as_uint(x);
    asm("mov.b64 %0, {%1, %1};" : "=l"(r) : "r"(u));
    return r;
}
__device__ __forceinline__ ull pkxy(float x, float y) {
    ull r;
    asm("mov.b64 %0, {%1, %2};" : "=l"(r) : "r"(__float_as_uint(x)), "r"(__float_as_uint(y)));
    return r;
}
__device__ __forceinline__ void upk(ull v, float& x, float& y) {
    unsigned a, b;
    asm("mov.b64 {%0, %1}, %2;" : "=r"(a), "=r"(b) : "l"(v));
    x = __uint_as_float(a); y = __uint_as_float(b);
}
#define FMA2(d, a, b) asm("fma.rn.f32x2 %0, %1, %2, %0;" : "+l"(d) : "l"(a), "l"(b))
#define ADD2(d, a, b) asm("add.rn.f32x2 %0, %1, %2;" : "=l"(d) : "l"(a), "l"(b))
#define U0(v) (((ull*)&(v))[0])
#define U1(v) (((ull*)&(v))[1])

// ---------------- device scratch ----------------
__device__ float g_h[(size_t)NN * 256];
__device__ float g_z1[(size_t)NN * 64];
__device__ float g_sc[(size_t)EE * 4];    // CSR-ordered scores
__device__ float g_ss[NN * 4];
__device__ float g_sd[NN * 4];
__device__ int   g_cnt[NN];
__device__ int   g_rowptr[NN + 1];
__device__ int   g_cur[NN];
__device__ int   g_pos[EE];               // edge -> CSR slot
__device__ int4  g_mt[EE];                // CSR slot -> (src, etype, orig, 0)
__device__ float g_wae1[64], g_tae1[88];
__device__ float g_wae2[64], g_tae2[88];

// ---------------- CSR build ----------------
__global__ void k_count(const int* __restrict__ ei) {
    int e = blockIdx.x * blockDim.x + threadIdx.x;
    if (e < EE) atomicAdd(&g_cnt[ei[EE + e]], 1);
}

__global__ void k_scanfuse(const float* __restrict__ We1, const float* __restrict__ ae1,
                           const float* __restrict__ et1,
                           const float* __restrict__ We2, const float* __restrict__ ae2,
                           const float* __restrict__ et2) {
    __shared__ int sp[1024];
    int tid = threadIdx.x;
    if (tid < 64) {
        int k = tid >> 2, h = tid & 3;
        float s = 0.f;
        for (int d = 0; d < 16; d++) s += We1[k * 64 + h * 16 + d] * ae1[h * 16 + d];
        g_wae1[k * 4 + h] = s;
        float s2 = 0.f;
        for (int d = 0; d < 64; d++) s2 += We2[k * 256 + h * 64 + d] * ae2[h * 64 + d];
        g_wae2[k * 4 + h] = s2;
    }
    if (tid < 88) {
        int t = tid >> 2, h = tid & 3;
        float s = 0.f;
        for (int d = 0; d < 16; d++) s += et1[t * 64 + h * 16 + d] * ae1[h * 16 + d];
        g_tae1[t * 4 + h] = s;
        float s2 = 0.f;
        for (int d = 0; d < 64; d++) s2 += et2[t * 256 + h * 64 + d] * ae2[h * 64 + d];
        g_tae2[t * 4 + h] = s2;
    }
    const int chunk = (NN + 1023) >> 10;
    int st = tid * chunk;
    int en = st + chunk; if (en > NN) en = NN;
    int s = 0;
    for (int i = st; i < en; i++) s += g_cnt[i];
    sp[tid] = s;
    __syncthreads();
    for (int o = 1; o < 1024; o <<= 1) {
        int v = (tid >= o) ? sp[tid - o] : 0;
        __syncthreads();
        sp[tid] += v;
        __syncthreads();
    }
    int b = sp[tid] - s;
    for (int i = st; i < en; i++) {
        g_rowptr[i] = b; g_cur[i] = b; b += g_cnt[i];
        g_cnt[i] = 0;   // re-zero for next replay (graph-invariant)
    }
    if (tid == 1023) g_rowptr[NN] = sp[1023];
}

__global__ void k_fill(const int* __restrict__ ei, const int* __restrict__ etype) {
    int e = blockIdx.x * blockDim.x + threadIdx.x;
    if (e < EE) {
        int d = ei[EE + e];
        int p = atomicAdd(&g_cur[d], 1);
        g_pos[e] = p;
        g_mt[p] = make_int4(ei[e], etype[e], e, 0);
    }
}

// ---------------- layer1 node projection + ss/sd dots ----------------
__global__ void k_proj1(const float* __restrict__ x, const int* __restrict__ ntype,
                        const float* __restrict__ nt, const float* __restrict__ Wx,
                        const float* __restrict__ a_s, const float* __restrict__ a_d) {
    __shared__ float sWx[16 * 64];
    __shared__ float sNt[8 * 16];
    __shared__ float sAs[64];
    __shared__ float sAd[64];
    __shared__ float sStage[8 * 16];

    int tid = threadIdx.x;
    for (int i = tid; i < 16 * 64; i += 256) sWx[i] = Wx[i];
    for (int i = tid; i < 8 * 16; i += 256) sNt[i] = nt[i];
    if (tid < 64) { sAs[tid] = a_s[tid]; sAd[tid] = a_d[tid]; }
    __syncthreads();

    int warp = tid >> 5, lane = tid & 31;
    int n = blockIdx.x * 8 + warp;
    if (n >= NN) return;

    float* st = sStage + warp * 16;
    int t = ntype[n];
    if (lane < 16) st[lane] = x[(size_t)n * 16 + lane] + sNt[t * 16 + lane];
    __syncwarp();

    float acc0 = 0.f, acc1 = 0.f;
#pragma unroll
    for (int k = 0; k < 16; k++) {
        float xk = st[k];
        acc0 = fmaf(xk, sWx[k * 64 + lane], acc0);
        acc1 = fmaf(xk, sWx[k * 64 + lane + 32], acc1);
    }
    g_h[(size_t)n * 64 + lane] = acc0;
    g_h[(size_t)n * 64 + lane + 32] = acc1;

    float pa = acc0 * sAs[lane], pb = acc1 * sAs[lane + 32];
    float qa = acc0 * sAd[lane], qb = acc1 * sAd[lane + 32];
#pragma unroll
    for (int o = 8; o >= 1; o >>= 1) {
        pa += __shfl_xor_sync(0xffffffffu, pa, o);
        pb += __shfl_xor_sync(0xffffffffu, pb, o);
        qa += __shfl_xor_sync(0xffffffffu, qa, o);
        qb += __shfl_xor_sync(0xffffffffu, qb, o);
    }
    if (lane == 0)  { g_ss[n * 4 + 0] = pa; g_ss[n * 4 + 2] = pb; g_sd[n * 4 + 0] = qa; g_sd[n * 4 + 2] = qb; }
    if (lane == 16) { g_ss[n * 4 + 1] = pa; g_ss[n * 4 + 3] = pb; g_sd[n * 4 + 1] = qa; g_sd[n * 4 + 3] = qb; }
}

// ---------------- edge scores (packed f32x2), scattered to CSR slots ----------------
template <int LAYER>
__global__ void k_score(const int* __restrict__ ei, const float* __restrict__ eattr,
                        const int* __restrict__ etype) {
    __shared__ __align__(16) float sW[64];
    __shared__ float sT[88];
    const float* wae = (LAYER == 1) ? g_wae1 : g_wae2;
    const float* tae = (LAYER == 1) ? g_tae1 : g_tae2;
    if (threadIdx.x < 64) sW[threadIdx.x] = wae[threadIdx.x];
    if (threadIdx.x < 88) sT[threadIdx.x] = tae[threadIdx.x];
    __syncthreads();
    const ull* sWp = (const ull*)sW;

    int e = blockIdx.x * blockDim.x + threadIdx.x;
    if (e >= EE) return;
    int s = ei[e], d = ei[EE + e], t = etype[e];
    float c0 = g_ss[s * 4 + 0] + g_sd[d * 4 + 0] + sT[t * 4 + 0];
    float c1 = g_ss[s * 4 + 1] + g_sd[d * 4 + 1] + sT[t * 4 + 1];
    float c2 = g_ss[s * 4 + 2] + g_sd[d * 4 + 2] + sT[t * 4 + 2];
    float c3 = g_ss[s * 4 + 3] + g_sd[d * 4 + 3] + sT[t * 4 + 3];
    ull s01 = pkxy(c0, c1), s23 = pkxy(c2, c3);

    const float4* ea = (const float4*)(eattr + (size_t)e * 16);
#pragma unroll
    for (int q = 0; q < 4; q++) {
        float4 a = __ldg(ea + q);
        ull p;
        p = pk2(a.x); FMA2(s01, p, sWp[(4 * q + 0) * 2]); FMA2(s23, p, sWp[(4 * q + 0) * 2 + 1]);
        p = pk2(a.y); FMA2(s01, p, sWp[(4 * q + 1) * 2]); FMA2(s23, p, sWp[(4 * q + 1) * 2 + 1]);
        p = pk2(a.z); FMA2(s01, p, sWp[(4 * q + 2) * 2]); FMA2(s23, p, sWp[(4 * q + 2) * 2 + 1]);
        p = pk2(a.w); FMA2(s01, p, sWp[(4 * q + 3) * 2]); FMA2(s23, p, sWp[(4 * q + 3) * 2 + 1]);
    }
    float sc[4];
    upk(s01, sc[0], sc[1]); upk(s23, sc[2], sc[3]);
#pragma unroll
    for (int h = 0; h < 4; h++) sc[h] = (sc[h] > 0.f) ? sc[h] : 0.2f * sc[h];
    int p = __ldg(&g_pos[e]);
    *(float4*)&g_sc[(size_t)p * 4] = make_float4(sc[0], sc[1], sc[2], sc[3]);
}

// ---------------- layer1 aggregation: persistent warps, fused softmax, 4-edge MLP ----------------
__global__ void __launch_bounds__(256) k_agg1(const float* __restrict__ eattr,
                                              const float* __restrict__ We, const float* __restrict__ et,
                                              const float* __restrict__ x, const float* __restrict__ res) {
    __shared__ __align__(16) float sEt[22 * 64];
    __shared__ __align__(16) float sWe[16 * 64];
    __shared__ __align__(16) float sRes[16 * 64];
    __shared__ float sWs[8 * 64];
    __shared__ float4 sAl[8][32];
    __shared__ int4 sMt[8][32];
    int tid = threadIdx.x, L = tid & 31, w = tid >> 5;
    for (int i = tid; i < 22 * 64; i += 256) sEt[i] = et[i];
    for (int i = tid; i < 16 * 64; i += 256) { sWe[i] = We[i]; sRes[i] = res[i]; }
    __syncthreads();

    const int H = L >> 3, hb = L >> 4;
    for (int n = blockIdx.x * 8 + w; n < NN; n += gridDim.x * 8) {
        int r0 = __ldg(&g_rowptr[n]), r1 = __ldg(&g_rowptr[n + 1]);

        float m[4] = {-3e38f, -3e38f, -3e38f, -3e38f}, dd[4] = {0.f, 0.f, 0.f, 0.f};
        for (int i = r0 + L; i < r1; i += 32) {
            float4 s = *(const float4*)&g_sc[(size_t)i * 4];
            float sv[4] = {s.x, s.y, s.z, s.w};
#pragma unroll
            for (int h = 0; h < 4; h++) {
                if (sv[h] > m[h]) { dd[h] *= __expf(m[h] - sv[h]); m[h] = sv[h]; }
                dd[h] += __expf(sv[h] - m[h]);
            }
        }
#pragma unroll
        for (int o = 16; o >= 1; o >>= 1) {
#pragma unroll
            for (int h = 0; h < 4; h++) {
                float mo = __shfl_xor_sync(0xffffffffu, m[h], o);
                float d_o = __shfl_xor_sync(0xffffffffu, dd[h], o);
                float mn = fmaxf(m[h], mo);
                dd[h] = dd[h] * __expf(m[h] - mn) + d_o * __expf(mo - mn);
                m[h] = mn;
            }
        }
        float inv[4];
#pragma unroll
        for (int h = 0; h < 4; h++) inv[h] = 1.f / (dd[h] + 1e-16f);

        ull Acc = 0;
        float w0 = 0.f, w1 = 0.f;
        for (int base = r0; base < r1; base += 32) {
            int nv = min(32, r1 - base);
            if (L < nv) {
                float4 s = *(const float4*)&g_sc[(size_t)(base + L) * 4];
                sAl[w][L] = make_float4(__expf(s.x - m[0]) * inv[0], __expf(s.y - m[1]) * inv[1],
                                        __expf(s.z - m[2]) * inv[2], __expf(s.w - m[3]) * inv[3]);
                sMt[w][L] = g_mt[base + L];
            }
            __syncwarp();
            for (int j0 = 0; j0 < nv; j0 += 4) {
                int c4 = min(4, nv - j0);
                float2 H2[4]; float EA[4]; float4 AL[4]; int TJ[4];
#pragma unroll
                for (int q = 0; q < 4; q++) {
                    if (q < c4) {
                        int4 mt = sMt[w][j0 + q];
                        TJ[q] = mt.y;
                        H2[q] = *(const float2*)&g_h[(size_t)mt.x * 64 + 2 * L];
                        EA[q] = __ldg(&eattr[(size_t)mt.z * 16 + (L & 15)]);
                        AL[q] = sAl[w][j0 + q];
                    }
                }
#pragma unroll
                for (int q = 0; q < 4; q++) {
                    if (q < c4) {
                        float2 ev = *(const float2*)&sEt[TJ[q] * 64 + 2 * L];
                        float ah = (H == 0) ? AL[q].x : ((H == 1) ? AL[q].y : ((H == 2) ? AL[q].z : AL[q].w));
                        ull t; ADD2(t, U0(H2[q]), U0(ev));
                        FMA2(Acc, pk2(ah), t);
                        float aw0 = hb ? AL[q].y : AL[q].x, aw1 = hb ? AL[q].w : AL[q].z;
                        w0 = fmaf(aw0, EA[q], w0);
                        w1 = fmaf(aw1, EA[q], w1);
                    }
                }
            }
            __syncwarp();
        }
        sWs[w * 64 + L] = w0;
        sWs[w * 64 + 32 + L] = w1;
        __syncwarp();
#pragma unroll
        for (int k = 0; k < 16; k++) {
            float wk = sWs[w * 64 + H * 16 + k];
            float2 we = *(const float2*)&sWe[k * 64 + 2 * L];
            FMA2(Acc, pk2(wk), U0(we));
        }
        const float4* xp = (const float4*)(x + (size_t)n * 16);
        float4 xa = __ldg(xp), xb = __ldg(xp + 1), xc = __ldg(xp + 2), xd = __ldg(xp + 3);
        float xv[16] = {xa.x, xa.y, xa.z, xa.w, xb.x, xb.y, xb.z, xb.w,
                        xc.x, xc.y, xc.z, xc.w, xd.x, xd.y, xd.z, xd.w};
#pragma unroll
        for (int k = 0; k < 16; k++) {
            float2 rv = *(const float2*)&sRes[k * 64 + 2 * L];
            FMA2(Acc, pk2(xv[k]), U0(rv));
        }
        float ax, ay; upk(Acc, ax, ay);
        float2 o = make_float2(fmaxf(ax, 0.f), fmaxf(ay, 0.f));
        *(float2*)&g_z1[(size_t)n * 64 + 2 * L] = o;
        __syncwarp();
    }
}

// ---------------- layer2 projection: tiled GEMM (f32x2) + fused ss/sd ----------------
__global__ void __launch_bounds__(256) k_proj2(const int* __restrict__ ntype, const float* __restrict__ nt,
                                               const float* __restrict__ Wx,
                                               const float* __restrict__ a_s, const float* __restrict__ a_d) {
    extern __shared__ float sm[];
    float* sA = sm;              // 128*68
    float* sB = sA + 128 * 68;   // 64*64
    float* sNt = sB + 4096;      // 8*64
    float* sAs = sNt + 512;      // 64
    float* sAd = sAs + 64;       // 64
    int*   sTy = (int*)(sAd + 64); // 128

    int tid = threadIdx.x;
    int by = blockIdx.y;
    int rbase = blockIdx.x * 128;

    for (int i = tid; i < 512; i += 256) sNt[i] = nt[i];
    if (tid < 64) { sAs[tid] = a_s[by * 64 + tid]; sAd[tid] = a_d[by * 64 + tid]; }
    if (tid < 128) { int r = rbase + tid; sTy[tid] = (r < NN) ? ntype[r] : 0; }
    __syncthreads();

    for (int i = tid; i < 1024; i += 256) {
        int k = i >> 4, cg = i & 15;
        float4 v = *(const float4*)&Wx[(size_t)k * 256 + by * 64 + cg * 4];
        *(float4*)&sB[k * 64 + cg * 4] = v;
    }
    for (int i = tid; i < 2048; i += 256) {
        int r = i >> 4, sg = i & 15;
        int gr = rbase + r;
        float4 v = make_float4(0.f, 0.f, 0.f, 0.f);
        if (gr < NN) {
            v = *(const float4*)&g_z1[(size_t)gr * 64 + sg * 4];
            float4 nv = *(const float4*)&sNt[sTy[r] * 64 + sg * 4];
            v.x += nv.x; v.y += nv.y; v.z += nv.z; v.w += nv.w;
        }
        *(float4*)&sA[r * 68 + sg * 4] = v;
    }
    __syncthreads();

    int tx = tid & 15, ty = tid >> 4;
    int c0 = tx * 4, r0 = ty * 8;
    float4 acc[8];
#pragma unroll
    for (int i = 0; i < 8; i++) acc[i] = make_float4(0.f, 0.f, 0.f, 0.f);

    for (int k = 0; k < 64; k += 4) {
        float4 B[4];
#pragma unroll
        for (int kk = 0; kk < 4; kk++) B[kk] = *(const float4*)&sB[(k + kk) * 64 + c0];
#pragma unroll
        for (int i = 0; i < 8; i++) {
            float4 av = *(const float4*)&sA[(r0 + i) * 68 + k];
            ull p;
            p = pk2(av.x); FMA2(U0(acc[i]), p, U0(B[0])); FMA2(U1(acc[i]), p, U1(B[0]));
            p = pk2(av.y); FMA2(U0(acc[i]), p, U0(B[1])); FMA2(U1(acc[i]), p, U1(B[1]));
            p = pk2(av.z); FMA2(U0(acc[i]), p, U0(B[2])); FMA2(U1(acc[i]), p, U1(B[2]));
            p = pk2(av.w); FMA2(U0(acc[i]), p, U0(B[3])); FMA2(U1(acc[i]), p, U1(B[3]));
        }
    }

    float ps[8], pd[8];
#pragma unroll
    for (int i = 0; i < 8; i++) {
        int gr = rbase + r0 + i;
        if (gr < NN) *(float4*)&g_h[(size_t)gr * 256 + by * 64 + c0] = acc[i];
        ps[i] = acc[i].x * sAs[c0] + acc[i].y * sAs[c0 + 1] + acc[i].z * sAs[c0 + 2] + acc[i].w * sAs[c0 + 3];
        pd[i] = acc[i].x * sAd[c0] + acc[i].y * sAd[c0 + 1] + acc[i].z * sAd[c0 + 2] + acc[i].w * sAd[c0 + 3];
    }
#pragma unroll
    for (int o = 1; o < 16; o <<= 1) {
#pragma unroll
        for (int i = 0; i < 8; i++) {
            ps[i] += __shfl_xor_sync(0xffffffffu, ps[i], o);
            pd[i] += __shfl_xor_sync(0xffffffffu, pd[i], o);
        }
    }
    if (tx == 0) {
#pragma unroll
        for (int i = 0; i < 8; i++) {
            int gr = rbase + r0 + i;
            if (gr < NN) { g_ss[gr * 4 + by] = ps[i]; g_sd[gr * 4 + by] = pd[i]; }
        }
    }
}

// ---------------- layer2 aggregation: persistent warps, fused softmax, 4-edge MLP ----------------
__global__ void __launch_bounds__(256) k_agg2(const float* __restrict__ eattr,
                                              const float* __restrict__ We, const float* __restrict__ et,
                                              float* __restrict__ zout) {
    __shared__ float4 sEt[22 * 64];
    __shared__ float4 sWe[16 * 64];
    __shared__ float  sWs[8 * 64];
    __shared__ float4 sAl[8][32];
    __shared__ int4 sMt[8][32];
    int tid = threadIdx.x, L = tid & 31, w = tid >> 5;
    for (int i = tid; i < 22 * 64; i += 256) sEt[i] = *(const float4*)&et[(size_t)i * 4];
    for (int i = tid; i < 16 * 64; i += 256) sWe[i] = *(const float4*)&We[(size_t)i * 4];
    __syncthreads();

    const int hb = L >> 4;
    for (int n = blockIdx.x * 8 + w; n < NN; n += gridDim.x * 8) {
        int r0 = __ldg(&g_rowptr[n]), r1 = __ldg(&g_rowptr[n + 1]);

        float m[4] = {-3e38f, -3e38f, -3e38f, -3e38f}, dd[4] = {0.f, 0.f, 0.f, 0.f};
        for (int i = r0 + L; i < r1; i += 32) {
            float4 s = *(const float4*)&g_sc[(size_t)i * 4];
            float sv[4] = {s.x, s.y, s.z, s.w};
#pragma unroll
            for (int h = 0; h < 4; h++) {
                if (sv[h] > m[h]) { dd[h] *= __expf(m[h] - sv[h]); m[h] = sv[h]; }
                dd[h] += __expf(sv[h] - m[h]);
            }
        }
#pragma unroll
        for (int o = 16; o >= 1; o >>= 1) {
#pragma unroll
            for (int h = 0; h < 4; h++) {
                float mo = __shfl_xor_sync(0xffffffffu, m[h], o);
                float d_o = __shfl_xor_sync(0xffffffffu, dd[h], o);
                float mn = fmaxf(m[h], mo);
                dd[h] = dd[h] * __expf(m[h] - mn) + d_o * __expf(mo - mn);
                m[h] = mn;
            }
        }
        float inv[4];
#pragma unroll
        for (int h = 0; h < 4; h++) inv[h] = 1.f / (dd[h] + 1e-16f);

        ull A00 = 0, A01 = 0, A10 = 0, A11 = 0;
        float w0 = 0.f, w1 = 0.f;

        for (int base = r0; base < r1; base += 32) {
            int nv = min(32, r1 - base);
            if (L < nv) {
                float4 s = *(const float4*)&g_sc[(size_t)(base + L) * 4];
                sAl[w][L] = make_float4(__expf(s.x - m[0]) * inv[0], __expf(s.y - m[1]) * inv[1],
                                        __expf(s.z - m[2]) * inv[2], __expf(s.w - m[3]) * inv[3]);
                sMt[w][L] = g_mt[base + L];
            }
            __syncwarp();
            for (int j0 = 0; j0 < nv; j0 += 4) {
                int c4 = min(4, nv - j0);
                float4 H0[4], H1[4], AL[4]; float EA[4]; int TJ[4];
#pragma unroll
                for (int q = 0; q < 4; q++) {
                    if (q < c4) {
                        int4 mt = sMt[w][j0 + q];
                        TJ[q] = mt.y;
                        const float4* hp = (const float4*)(g_h + (size_t)mt.x * 256);
                        H0[q] = __ldg(hp + L);
                        H1[q] = __ldg(hp + 32 + L);
                        EA[q] = __ldg(&eattr[(size_t)mt.z * 16 + (L & 15)]);
                        AL[q] = sAl[w][j0 + q];
                    }
                }
#pragma unroll
                for (int q = 0; q < 4; q++) {
                    if (q < c4) {
                        float4 e0 = sEt[TJ[q] * 64 + L];
                        float4 e1 = sEt[TJ[q] * 64 + 32 + L];
                        float aA = hb ? AL[q].y : AL[q].x;
                        float aB = hb ? AL[q].w : AL[q].z;
                        ull ap = pk2(aA), bp = pk2(aB), t;
                        ADD2(t, U0(H0[q]), U0(e0)); FMA2(A00, ap, t);
                        ADD2(t, U1(H0[q]), U1(e0)); FMA2(A01, ap, t);
                        ADD2(t, U0(H1[q]), U0(e1)); FMA2(A10, bp, t);
                        ADD2(t, U1(H1[q]), U1(e1)); FMA2(A11, bp, t);
                        w0 = fmaf(aA, EA[q], w0);
                        w1 = fmaf(aB, EA[q], w1);
                    }
                }
            }
            __syncwarp();
        }
        sWs[w * 64 + L] = w0;
        sWs[w * 64 + 32 + L] = w1;
        __syncwarp();

        const int H0i = hb, H1i = 2 + hb;
#pragma unroll
        for (int k = 0; k < 16; k++) {
            ull k0 = pk2(sWs[w * 64 + H0i * 16 + k]);
            ull k1 = pk2(sWs[w * 64 + H1i * 16 + k]);
            float4 we0 = sWe[k * 64 + L];
            float4 we1 = sWe[k * 64 + 32 + L];
            FMA2(A00, k0, U0(we0)); FMA2(A01, k0, U1(we0));
            FMA2(A10, k1, U0(we1)); FMA2(A11, k1, U1(we1));
        }
        float4 acc0, acc1;
        U0(acc0) = A00; U1(acc0) = A01; U0(acc1) = A10; U1(acc1) = A11;
        float4 sm4;
        sm4.x = acc0.x + acc1.x; sm4.y = acc0.y + acc1.y;
        sm4.z = acc0.z + acc1.z; sm4.w = acc0.w + acc1.w;
        sm4.x += __shfl_xor_sync(0xffffffffu, sm4.x, 16);
        sm4.y += __shfl_xor_sync(0xffffffffu, sm4.y, 16);
        sm4.z += __shfl_xor_sync(0xffffffffu, sm4.z, 16);
        sm4.w += __shfl_xor_sync(0xffffffffu, sm4.w, 16);
        if (L < 16) {
            float4 z1v = *(const float4*)&g_z1[(size_t)n * 64 + 4 * L];
            float4 o;
            o.x = z1v.x + 0.25f * sm4.x;
            o.y = z1v.y + 0.25f * sm4.y;
            o.z = z1v.z + 0.25f * sm4.z;
            o.w = z1v.w + 0.25f * sm4.w;
            *(float4*)&zout[(size_t)n * 64 + 4 * L] = o;
        }
        __syncwarp();
    }
}

// ---------------- decoder: persistent tiled GEMM (f32x2), W1 resident ----------------
__global__ void __launch_bounds__(256) k_dec(const int* __restrict__ eli, const float* __restrict__ z,
                                             const float* __restrict__ W1, const float* __restrict__ b1,
                                             const float* __restrict__ W2, const float* __restrict__ b2,
                                             float* __restrict__ pred) {
    extern __shared__ float sm[];
    float* sA = sm;                 // 64*132
    float* sB = sA + 64 * 132;      // 128*64
    int*   sR = (int*)(sB + 8192);  // 64
    int*   sC = sR + 64;            // 64
    float* sb1 = (float*)(sC + 64); // 64
    float* sw2 = sb1 + 64;          // 64

    int tid = threadIdx.x;
    if (tid < 64) { sb1[tid] = b1[tid]; sw2[tid] = W2[tid]; }
    for (int i = tid; i < 2048; i += 256)
        *(float4*)&sB[i * 4] = *(const float4*)&W1[(size_t)i * 4];

    int tx = tid & 15, ty = tid >> 4;
    int c0 = tx * 4, r0 = ty * 4;
    float bb = __ldg(&b2[0]);

    const int NT = ELN / 64;
    for (int tile = blockIdx.x; tile < NT; tile += gridDim.x) {
        int ebase = tile * 64;
        __syncthreads();
        if (tid < 64) sR[tid] = __ldg(&eli[ebase + tid]);
        else if (tid < 128) sC[tid - 64] = __ldg(&eli[ELN + ebase + tid - 64]);
        __syncthreads();
        for (int i = tid; i < 2048; i += 256) {
            int e = i >> 5, sg = i & 31;
            int node = (sg < 16) ? sR[e] : sC[e];
            float4 v = *(const float4*)&z[(size_t)node * 64 + (sg & 15) * 4];
            *(float4*)&sA[e * 132 + sg * 4] = v;
        }
        __syncthreads();

        float4 acc[4];
#pragma unroll
        for (int i = 0; i < 4; i++) acc[i] = make_float4(0.f, 0.f, 0.f, 0.f);

        for (int k = 0; k < 128; k += 4) {
            float4 B[4];
#pragma unroll
            for (int kk = 0; kk < 4; kk++) B[kk] = *(const float4*)&sB[(k + kk) * 64 + c0];
#pragma unroll
            for (int i = 0; i < 4; i++) {
                float4 av = *(const float4*)&sA[(r0 + i) * 132 + k];
                ull p;
                p = pk2(av.x); FMA2(U0(acc[i]), p, U0(B[0])); FMA2(U1(acc[i]), p, U1(B[0]));
                p = pk2(av.y); FMA2(U0(acc[i]), p, U0(B[1])); FMA2(U1(acc[i]), p, U1(B[1]));
                p = pk2(av.z); FMA2(U0(acc[i]), p, U0(B[2])); FMA2(U1(acc[i]), p, U1(B[2]));
                p = pk2(av.w); FMA2(U0(acc[i]), p, U0(B[3])); FMA2(U1(acc[i]), p, U1(B[3]));
            }
        }

        float p[4];
#pragma unroll
        for (int i = 0; i < 4; i++) {
            float hx = fmaxf(acc[i].x + sb1[c0],     0.f);
            float hy = fmaxf(acc[i].y + sb1[c0 + 1], 0.f);
            float hz = fmaxf(acc[i].z + sb1[c0 + 2], 0.f);
            float hw = fmaxf(acc[i].w + sb1[c0 + 3], 0.f);
            p[i] = hx * sw2[c0] + hy * sw2[c0 + 1] + hz * sw2[c0 + 2] + hw * sw2[c0 + 3];
        }
#pragma unroll
        for (int o = 1; o < 16; o <<= 1) {
#pragma unroll
            for (int i = 0; i < 4; i++) p[i] += __shfl_xor_sync(0xffffffffu, p[i], o);
        }
        if (tx == 0) {
#pragma unroll
            for (int i = 0; i < 4; i++) pred[ebase + r0 + i] = p[i] + bb;
        }
    }
}

// ---------------- launch ----------------
extern "C" void kernel_launch(void* const* d_in, const int* in_sizes, int n_in,
                              void* d_out, int out_size) {
    const float* x     = (const float*)d_in[0];
    const int*   ei    = (const int*)d_in[1];
    const int*   ntype = (const int*)d_in[2];
    const float* eattr = (const float*)d_in[3];
    const int*   etype = (const int*)d_in[4];
    const int*   eli   = (const int*)d_in[5];
    const float* Wx1   = (const float*)d_in[6];
    const float* We1   = (const float*)d_in[7];
    const float* nt1   = (const float*)d_in[8];
    const float* et1   = (const float*)d_in[9];
    const float* as1   = (const float*)d_in[10];
    const float* ad1   = (const float*)d_in[11];
    const float* ae1   = (const float*)d_in[12];
    const float* res1  = (const float*)d_in[13];
    const float* Wx2   = (const float*)d_in[14];
    const float* We2   = (const float*)d_in[15];
    const float* nt2   = (const float*)d_in[16];
    const float* et2   = (const float*)d_in[17];
    const float* as2   = (const float*)d_in[18];
    const float* ad2   = (const float*)d_in[19];
    const float* ae2   = (const float*)d_in[20];
    const float* W1    = (const float*)d_in[21];
    const float* b1    = (const float*)d_in[22];
    const float* W2    = (const float*)d_in[23];
    const float* b2    = (const float*)d_in[24];

    float* pred = (float*)d_out;
    float* zout = pred + ELN;

    // CSR build (g_cnt is zeroed by previous scanfuse / static init)
    k_count<<<(EE + 255) / 256, 256>>>(ei);
    k_scanfuse<<<1, 1024>>>(We1, ae1, et1, We2, ae2, et2);
    k_fill<<<(EE + 255) / 256, 256>>>(ei, etype);

    // layer 1 (proj1 = 4th launch -> profiled slot)
    k_proj1<<<(NN + 7) / 8, 256>>>(x, ntype, nt1, Wx1, as1, ad1);
    k_score<1><<<(EE + 255) / 256, 256>>>(ei, eattr, etype);
    k_agg1<<<1184, 256>>>(eattr, We1, et1, x, res1);

    // layer 2
    size_t smP2 = (size_t)(128 * 68 + 64 * 64 + 512 + 64 + 64 + 128) * sizeof(float);
    cudaFuncSetAttribute((const void*)k_proj2, cudaFuncAttributeMaxDynamicSharedMemorySize, (int)smP2);
    k_proj2<<<dim3((NN + 127) / 128, 4), 256, smP2>>>(ntype, nt2, Wx2, as2, ad2);
    k_score<2><<<(EE + 255) / 256, 256>>>(ei, eattr, etype);
    k_agg2<<<1184, 256>>>(eattr, We2, et2, zout);

    // decoder
    size_t smD = (size_t)(64 * 132 + 128 * 64 + 64 + 64 + 64 + 64) * sizeof(float);
    cudaFuncSetAttribute((const void*)k_dec, cudaFuncAttributeMaxDynamicSharedMemorySize, (int)smD);
    k_dec<<<592, 256, smD>>>(eli, zout, W1, b1, W2, b2, pred);
}

// round 6
// speedup vs baseline: 1.0002x; 1.0002x over previous
#include <cuda_runtime.h>
#include <mma.h>
#include <cstdint>

using namespace nvcuda;

#define NN 100000
#define EE 600000
#define ELN 200000

// ---------------- device scratch ----------------
__device__ float g_h[(size_t)NN * 256];
__device__ float g_z1[(size_t)NN * 64];
__device__ float g_sc[(size_t)EE * 4];    // CSR-ordered scores
__device__ float g_ss[NN * 4];
__device__ float g_sd[NN * 4];
__device__ int   g_cnt[NN];
__device__ int   g_rowptr[NN + 1];
__device__ int   g_cur[NN];
__device__ int   g_pos[EE];
__device__ int4  g_mt[EE];                // CSR slot -> (src, etype, orig, 0)
__device__ float g_wae1[64], g_tae1[88];
__device__ float g_wae2[64], g_tae2[88];

// ---------------- CSR build ----------------
__global__ void k_count(const int* __restrict__ ei) {
    int e = blockIdx.x * blockDim.x + threadIdx.x;
    if (e < EE) atomicAdd(&g_cnt[ei[EE + e]], 1);
}

__global__ void k_scanfuse(const float* __restrict__ We1, const float* __restrict__ ae1,
                           const float* __restrict__ et1,
                           const float* __restrict__ We2, const float* __restrict__ ae2,
                           const float* __restrict__ et2) {
    __shared__ int sp[1024];
    int tid = threadIdx.x;
    if (tid < 64) {
        int k = tid >> 2, h = tid & 3;
        float s = 0.f;
        for (int d = 0; d < 16; d++) s += We1[k * 64 + h * 16 + d] * ae1[h * 16 + d];
        g_wae1[k * 4 + h] = s;
        float s2 = 0.f;
        for (int d = 0; d < 64; d++) s2 += We2[k * 256 + h * 64 + d] * ae2[h * 64 + d];
        g_wae2[k * 4 + h] = s2;
    }
    if (tid < 88) {
        int t = tid >> 2, h = tid & 3;
        float s = 0.f;
        for (int d = 0; d < 16; d++) s += et1[t * 64 + h * 16 + d] * ae1[h * 16 + d];
        g_tae1[t * 4 + h] = s;
        float s2 = 0.f;
        for (int d = 0; d < 64; d++) s2 += et2[t * 256 + h * 64 + d] * ae2[h * 64 + d];
        g_tae2[t * 4 + h] = s2;
    }
    const int chunk = (NN + 1023) >> 10;
    int st = tid * chunk;
    int en = st + chunk; if (en > NN) en = NN;
    int s = 0;
    for (int i = st; i < en; i++) s += g_cnt[i];
    sp[tid] = s;
    __syncthreads();
    for (int o = 1; o < 1024; o <<= 1) {
        int v = (tid >= o) ? sp[tid - o] : 0;
        __syncthreads();
        sp[tid] += v;
        __syncthreads();
    }
    int b = sp[tid] - s;
    for (int i = st; i < en; i++) {
        g_rowptr[i] = b; g_cur[i] = b; b += g_cnt[i];
        g_cnt[i] = 0;   // re-zero for next replay
    }
    if (tid == 1023) g_rowptr[NN] = sp[1023];
}

__global__ void k_fill(const int* __restrict__ ei, const int* __restrict__ etype) {
    int e = blockIdx.x * blockDim.x + threadIdx.x;
    if (e < EE) {
        int d = ei[EE + e];
        int p = atomicAdd(&g_cur[d], 1);
        g_pos[e] = p;
        g_mt[p] = make_int4(ei[e], etype[e], e, 0);
    }
}

// ---------------- layer1 node projection: persistent, Wx in registers ----------------
__global__ void __launch_bounds__(256) k_proj1(const float* __restrict__ x, const int* __restrict__ ntype,
                                               const float* __restrict__ nt, const float* __restrict__ Wx,
                                               const float* __restrict__ a_s, const float* __restrict__ a_d) {
    __shared__ float sNt[8 * 16];
    int tid = threadIdx.x, L = tid & 31, w = tid >> 5;
    for (int i = tid; i < 128; i += 256) sNt[i] = nt[i];

    float W0[16], W1r[16];
#pragma unroll
    for (int k = 0; k < 16; k++) {
        W0[k]  = __ldg(&Wx[k * 64 + L]);
        W1r[k] = __ldg(&Wx[k * 64 + 32 + L]);
    }
    float as0 = __ldg(&a_s[L]), as1 = __ldg(&a_s[32 + L]);
    float ad0 = __ldg(&a_d[L]), ad1 = __ldg(&a_d[32 + L]);
    __syncthreads();

    int nwarps = gridDim.x * 8;
    for (int n = blockIdx.x * 8 + w; n < NN; n += nwarps) {
        int t = __ldg(&ntype[n]);
        float xv = 0.f;
        if (L < 16) xv = __ldg(&x[(size_t)n * 16 + L]) + sNt[t * 16 + L];
        float acc0 = 0.f, acc1 = 0.f;
#pragma unroll
        for (int k = 0; k < 16; k++) {
            float xk = __shfl_sync(0xffffffffu, xv, k);
            acc0 = fmaf(xk, W0[k], acc0);
            acc1 = fmaf(xk, W1r[k], acc1);
        }
        g_h[(size_t)n * 64 + L] = acc0;
        g_h[(size_t)n * 64 + 32 + L] = acc1;

        float pa = acc0 * as0, pb = acc1 * as1;
        float qa = acc0 * ad0, qb = acc1 * ad1;
#pragma unroll
        for (int o = 8; o >= 1; o >>= 1) {
            pa += __shfl_xor_sync(0xffffffffu, pa, o);
            pb += __shfl_xor_sync(0xffffffffu, pb, o);
            qa += __shfl_xor_sync(0xffffffffu, qa, o);
            qb += __shfl_xor_sync(0xffffffffu, qb, o);
        }
        if (L == 0)  { g_ss[n * 4 + 0] = pa; g_ss[n * 4 + 2] = pb; g_sd[n * 4 + 0] = qa; g_sd[n * 4 + 2] = qb; }
        if (L == 16) { g_ss[n * 4 + 1] = pa; g_ss[n * 4 + 3] = pb; g_sd[n * 4 + 1] = qa; g_sd[n * 4 + 3] = qb; }
    }
}

// ---------------- edge scores (scalar), scattered to CSR slots ----------------
template <int LAYER>
__global__ void k_score(const int* __restrict__ ei, const float* __restrict__ eattr,
                        const int* __restrict__ etype) {
    __shared__ float sW[64];
    __shared__ float sT[88];
    const float* wae = (LAYER == 1) ? g_wae1 : g_wae2;
    const float* tae = (LAYER == 1) ? g_tae1 : g_tae2;
    if (threadIdx.x < 64) sW[threadIdx.x] = wae[threadIdx.x];
    if (threadIdx.x < 88) sT[threadIdx.x] = tae[threadIdx.x];
    __syncthreads();

    int e = blockIdx.x * blockDim.x + threadIdx.x;
    if (e >= EE) return;
    int s = ei[e], d = ei[EE + e], t = etype[e];
    float4 ssv = *(const float4*)&g_ss[s * 4];
    float4 sdv = *(const float4*)&g_sd[d * 4];
    float sc[4];
    sc[0] = ssv.x + sdv.x + sT[t * 4 + 0];
    sc[1] = ssv.y + sdv.y + sT[t * 4 + 1];
    sc[2] = ssv.z + sdv.z + sT[t * 4 + 2];
    sc[3] = ssv.w + sdv.w + sT[t * 4 + 3];

    const float4* ea = (const float4*)(eattr + (size_t)e * 16);
#pragma unroll
    for (int q = 0; q < 4; q++) {
        float4 a = __ldg(ea + q);
#pragma unroll
        for (int h = 0; h < 4; h++) {
            sc[h] = fmaf(a.x, sW[(4 * q + 0) * 4 + h],
                    fmaf(a.y, sW[(4 * q + 1) * 4 + h],
                    fmaf(a.z, sW[(4 * q + 2) * 4 + h],
                    fmaf(a.w, sW[(4 * q + 3) * 4 + h], sc[h]))));
        }
    }
#pragma unroll
    for (int h = 0; h < 4; h++) sc[h] = (sc[h] > 0.f) ? sc[h] : 0.2f * sc[h];
    int p = __ldg(&g_pos[e]);
    *(float4*)&g_sc[(size_t)p * 4] = make_float4(sc[0], sc[1], sc[2], sc[3]);
}

// ---------------- layer1 aggregation ----------------
__global__ void __launch_bounds__(256) k_agg1(const float* __restrict__ eattr,
                                              const float* __restrict__ We, const float* __restrict__ et,
                                              const float* __restrict__ x, const float* __restrict__ res) {
    __shared__ float sEt[22 * 64];
    __shared__ float sWe[16 * 64];
    __shared__ float sRes[16 * 64];
    __shared__ float sWs[8 * 64];
    __shared__ float4 sAl[8][32];
    __shared__ int4 sMt[8][32];
    int tid = threadIdx.x, L = tid & 31, w = tid >> 5;
    for (int i = tid; i < 22 * 64; i += 256) sEt[i] = et[i];
    for (int i = tid; i < 16 * 64; i += 256) { sWe[i] = We[i]; sRes[i] = res[i]; }
    __syncthreads();

    const int H = L >> 3, hb = L >> 4;
    for (int n = blockIdx.x * 8 + w; n < NN; n += gridDim.x * 8) {
        int r0 = __ldg(&g_rowptr[n]), r1 = __ldg(&g_rowptr[n + 1]);

        float m[4] = {-3e38f, -3e38f, -3e38f, -3e38f}, dd[4] = {0.f, 0.f, 0.f, 0.f};
        for (int i = r0 + L; i < r1; i += 32) {
            float4 s = *(const float4*)&g_sc[(size_t)i * 4];
            float sv[4] = {s.x, s.y, s.z, s.w};
#pragma unroll
            for (int h = 0; h < 4; h++) {
                if (sv[h] > m[h]) { dd[h] *= __expf(m[h] - sv[h]); m[h] = sv[h]; }
                dd[h] += __expf(sv[h] - m[h]);
            }
        }
#pragma unroll
        for (int o = 16; o >= 1; o >>= 1) {
#pragma unroll
            for (int h = 0; h < 4; h++) {
                float mo = __shfl_xor_sync(0xffffffffu, m[h], o);
                float d_o = __shfl_xor_sync(0xffffffffu, dd[h], o);
                float mn = fmaxf(m[h], mo);
                dd[h] = dd[h] * __expf(m[h] - mn) + d_o * __expf(mo - mn);
                m[h] = mn;
            }
        }
        float inv[4];
#pragma unroll
        for (int h = 0; h < 4; h++) inv[h] = 1.f / (dd[h] + 1e-16f);

        float ax = 0.f, ay = 0.f;
        float w0 = 0.f, w1 = 0.f;
        for (int base = r0; base < r1; base += 32) {
            int nv = min(32, r1 - base);
            if (L < nv) {
                float4 s = *(const float4*)&g_sc[(size_t)(base + L) * 4];
                sAl[w][L] = make_float4(__expf(s.x - m[0]) * inv[0], __expf(s.y - m[1]) * inv[1],
                                        __expf(s.z - m[2]) * inv[2], __expf(s.w - m[3]) * inv[3]);
                sMt[w][L] = g_mt[base + L];
            }
            __syncwarp();
            for (int j0 = 0; j0 < nv; j0 += 4) {
                int c4 = min(4, nv - j0);
                float2 H2[4]; float EA[4]; float4 AL[4]; int TJ[4];
#pragma unroll
                for (int q = 0; q < 4; q++) {
                    if (q < c4) {
                        int4 mt = sMt[w][j0 + q];
                        TJ[q] = mt.y;
                        H2[q] = *(const float2*)&g_h[(size_t)mt.x * 64 + 2 * L];
                        EA[q] = __ldg(&eattr[(size_t)mt.z * 16 + (L & 15)]);
                        AL[q] = sAl[w][j0 + q];
                    }
                }
#pragma unroll
                for (int q = 0; q < 4; q++) {
                    if (q < c4) {
                        float2 ev = *(const float2*)&sEt[TJ[q] * 64 + 2 * L];
                        float ah = (H == 0) ? AL[q].x : ((H == 1) ? AL[q].y : ((H == 2) ? AL[q].z : AL[q].w));
                        ax = fmaf(ah, H2[q].x + ev.x, ax);
                        ay = fmaf(ah, H2[q].y + ev.y, ay);
                        float aw0 = hb ? AL[q].y : AL[q].x, aw1 = hb ? AL[q].w : AL[q].z;
                        w0 = fmaf(aw0, EA[q], w0);
                        w1 = fmaf(aw1, EA[q], w1);
                    }
                }
            }
            __syncwarp();
        }
        sWs[w * 64 + L] = w0;
        sWs[w * 64 + 32 + L] = w1;
        __syncwarp();
#pragma unroll
        for (int k = 0; k < 16; k++) {
            float wk = sWs[w * 64 + H * 16 + k];
            float2 we = *(const float2*)&sWe[k * 64 + 2 * L];
            ax = fmaf(wk, we.x, ax);
            ay = fmaf(wk, we.y, ay);
        }
        const float4* xp = (const float4*)(x + (size_t)n * 16);
        float4 xa = __ldg(xp), xb = __ldg(xp + 1), xc = __ldg(xp + 2), xd = __ldg(xp + 3);
        float xv[16] = {xa.x, xa.y, xa.z, xa.w, xb.x, xb.y, xb.z, xb.w,
                        xc.x, xc.y, xc.z, xc.w, xd.x, xd.y, xd.z, xd.w};
#pragma unroll
        for (int k = 0; k < 16; k++) {
            float2 rv = *(const float2*)&sRes[k * 64 + 2 * L];
            ax = fmaf(xv[k], rv.x, ax);
            ay = fmaf(xv[k], rv.y, ay);
        }
        *(float2*)&g_z1[(size_t)n * 64 + 2 * L] = make_float2(fmaxf(ax, 0.f), fmaxf(ay, 0.f));
        __syncwarp();
    }
}

// ---------------- layer2 projection: wmma tf32 GEMM + fused ss/sd ----------------
__global__ void __launch_bounds__(256) k_proj2(const int* __restrict__ ntype, const float* __restrict__ nt,
                                               const float* __restrict__ Wx,
                                               const float* __restrict__ a_s, const float* __restrict__ a_d) {
    extern __shared__ float sm[];
    float* sA = sm;              // 128*72 (input rows, later reused per-warp for C)
    float* sB = sA + 128 * 72;   // 64*64 Wx slice (k-major)
    float* sNt = sB + 4096;      // 8*64
    float* sAs = sNt + 512;      // 64
    float* sAd = sAs + 64;       // 64
    int*   sTy = (int*)(sAd + 64); // 128

    int tid = threadIdx.x, L = tid & 31, w = tid >> 5;
    int by = blockIdx.y;
    int rbase = blockIdx.x * 128;

    for (int i = tid; i < 512; i += 256) sNt[i] = nt[i];
    if (tid < 64) { sAs[tid] = a_s[by * 64 + tid]; sAd[tid] = a_d[by * 64 + tid]; }
    if (tid < 128) { int r = rbase + tid; sTy[tid] = (r < NN) ? ntype[r] : 0; }
    for (int i = tid; i < 1024; i += 256) {
        int k = i >> 4, cg = i & 15;
        float4 v = *(const float4*)&Wx[(size_t)k * 256 + by * 64 + cg * 4];
        *(float4*)&sB[k * 64 + cg * 4] = v;
    }
    __syncthreads();
    for (int i = tid; i < 2048; i += 256) {
        int r = i >> 4, sg = i & 15;
        int gr = rbase + r;
        float4 v = make_float4(0.f, 0.f, 0.f, 0.f);
        if (gr < NN) {
            v = *(const float4*)&g_z1[(size_t)gr * 64 + sg * 4];
            float4 nv = *(const float4*)&sNt[sTy[r] * 64 + sg * 4];
            v.x += nv.x; v.y += nv.y; v.z += nv.z; v.w += nv.w;
        }
        *(float4*)&sA[r * 72 + sg * 4] = v;
    }
    __syncthreads();

    // warp w computes rows w*16..w*16+15, all 64 cols
    wmma::fragment<wmma::accumulator, 16, 16, 8, float> fc[4];
#pragma unroll
    for (int c = 0; c < 4; c++) wmma::fill_fragment(fc[c], 0.f);
    for (int k0 = 0; k0 < 64; k0 += 8) {
        wmma::fragment<wmma::matrix_a, 16, 16, 8, wmma::precision::tf32, wmma::row_major> fa;
        wmma::load_matrix_sync(fa, &sA[w * 16 * 72 + k0], 72);
#pragma unroll
        for (int i = 0; i < fa.num_elements; i++) fa.x[i] = wmma::__float_to_tf32(fa.x[i]);
#pragma unroll
        for (int c = 0; c < 4; c++) {
            wmma::fragment<wmma::matrix_b, 16, 16, 8, wmma::precision::tf32, wmma::row_major> fb;
            wmma::load_matrix_sync(fb, &sB[k0 * 64 + c * 16], 64);
#pragma unroll
            for (int i = 0; i < fb.num_elements; i++) fb.x[i] = wmma::__float_to_tf32(fb.x[i]);
            wmma::mma_sync(fc[c], fa, fb, fc[c]);
        }
    }
    // store C into own rows of sA (warp-local: own fa loads complete)
    __syncwarp();
#pragma unroll
    for (int c = 0; c < 4; c++)
        wmma::store_matrix_sync(&sA[w * 16 * 72 + c * 16], fc[c], 72, wmma::mem_row_major);
    __syncwarp();

    // epilogue: write g_h + ss/sd dots
    for (int r = 0; r < 16; r++) {
        int gr = rbase + w * 16 + r;
        if (gr >= NN) break;
        float h0 = sA[(w * 16 + r) * 72 + L];
        float h1 = sA[(w * 16 + r) * 72 + 32 + L];
        g_h[(size_t)gr * 256 + by * 64 + L] = h0;
        g_h[(size_t)gr * 256 + by * 64 + 32 + L] = h1;
        float ps = h0 * sAs[L] + h1 * sAs[32 + L];
        float pd = h0 * sAd[L] + h1 * sAd[32 + L];
#pragma unroll
        for (int o = 16; o >= 1; o >>= 1) {
            ps += __shfl_xor_sync(0xffffffffu, ps, o);
            pd += __shfl_xor_sync(0xffffffffu, pd, o);
        }
        if (L == 0) { g_ss[gr * 4 + by] = ps; g_sd[gr * 4 + by] = pd; }
    }
}

// ---------------- layer2 aggregation ----------------
__global__ void __launch_bounds__(256) k_agg2(const float* __restrict__ eattr,
                                              const float* __restrict__ We, const float* __restrict__ et,
                                              float* __restrict__ zout) {
    __shared__ float4 sEt[22 * 64];
    __shared__ float4 sWe[16 * 64];
    __shared__ float  sWs[8 * 64];
    __shared__ float4 sAl[8][32];
    __shared__ int4 sMt[8][32];
    int tid = threadIdx.x, L = tid & 31, w = tid >> 5;
    for (int i = tid; i < 22 * 64; i += 256) sEt[i] = *(const float4*)&et[(size_t)i * 4];
    for (int i = tid; i < 16 * 64; i += 256) sWe[i] = *(const float4*)&We[(size_t)i * 4];
    __syncthreads();

    const int hb = L >> 4;
    for (int n = blockIdx.x * 8 + w; n < NN; n += gridDim.x * 8) {
        int r0 = __ldg(&g_rowptr[n]), r1 = __ldg(&g_rowptr[n + 1]);

        float m[4] = {-3e38f, -3e38f, -3e38f, -3e38f}, dd[4] = {0.f, 0.f, 0.f, 0.f};
        for (int i = r0 + L; i < r1; i += 32) {
            float4 s = *(const float4*)&g_sc[(size_t)i * 4];
            float sv[4] = {s.x, s.y, s.z, s.w};
#pragma unroll
            for (int h = 0; h < 4; h++) {
                if (sv[h] > m[h]) { dd[h] *= __expf(m[h] - sv[h]); m[h] = sv[h]; }
                dd[h] += __expf(sv[h] - m[h]);
            }
        }
#pragma unroll
        for (int o = 16; o >= 1; o >>= 1) {
#pragma unroll
            for (int h = 0; h < 4; h++) {
                float mo = __shfl_xor_sync(0xffffffffu, m[h], o);
                float d_o = __shfl_xor_sync(0xffffffffu, dd[h], o);
                float mn = fmaxf(m[h], mo);
                dd[h] = dd[h] * __expf(m[h] - mn) + d_o * __expf(mo - mn);
                m[h] = mn;
            }
        }
        float inv[4];
#pragma unroll
        for (int h = 0; h < 4; h++) inv[h] = 1.f / (dd[h] + 1e-16f);

        float4 acc0 = make_float4(0.f, 0.f, 0.f, 0.f);
        float4 acc1 = make_float4(0.f, 0.f, 0.f, 0.f);
        float w0 = 0.f, w1 = 0.f;

        for (int base = r0; base < r1; base += 32) {
            int nv = min(32, r1 - base);
            if (L < nv) {
                float4 s = *(const float4*)&g_sc[(size_t)(base + L) * 4];
                sAl[w][L] = make_float4(__expf(s.x - m[0]) * inv[0], __expf(s.y - m[1]) * inv[1],
                                        __expf(s.z - m[2]) * inv[2], __expf(s.w - m[3]) * inv[3]);
                sMt[w][L] = g_mt[base + L];
            }
            __syncwarp();
            for (int j0 = 0; j0 < nv; j0 += 4) {
                int c4 = min(4, nv - j0);
                float4 H0[4], H1[4], AL[4]; float EA[4]; int TJ[4];
#pragma unroll
                for (int q = 0; q < 4; q++) {
                    if (q < c4) {
                        int4 mt = sMt[w][j0 + q];
                        TJ[q] = mt.y;
                        const float4* hp = (const float4*)(g_h + (size_t)mt.x * 256);
                        H0[q] = __ldg(hp + L);
                        H1[q] = __ldg(hp + 32 + L);
                        EA[q] = __ldg(&eattr[(size_t)mt.z * 16 + (L & 15)]);
                        AL[q] = sAl[w][j0 + q];
                    }
                }
#pragma unroll
                for (int q = 0; q < 4; q++) {
                    if (q < c4) {
                        float4 e0 = sEt[TJ[q] * 64 + L];
                        float4 e1 = sEt[TJ[q] * 64 + 32 + L];
                        float aA = hb ? AL[q].y : AL[q].x;
                        float aB = hb ? AL[q].w : AL[q].z;
                        acc0.x = fmaf(aA, H0[q].x + e0.x, acc0.x);
                        acc0.y = fmaf(aA, H0[q].y + e0.y, acc0.y);
                        acc0.z = fmaf(aA, H0[q].z + e0.z, acc0.z);
                        acc0.w = fmaf(aA, H0[q].w + e0.w, acc0.w);
                        acc1.x = fmaf(aB, H1[q].x + e1.x, acc1.x);
                        acc1.y = fmaf(aB, H1[q].y + e1.y, acc1.y);
                        acc1.z = fmaf(aB, H1[q].z + e1.z, acc1.z);
                        acc1.w = fmaf(aB, H1[q].w + e1.w, acc1.w);
                        w0 = fmaf(aA, EA[q], w0);
                        w1 = fmaf(aB, EA[q], w1);
                    }
                }
            }
            __syncwarp();
        }
        sWs[w * 64 + L] = w0;
        sWs[w * 64 + 32 + L] = w1;
        __syncwarp();

        const int H0i = hb, H1i = 2 + hb;
#pragma unroll
        for (int k = 0; k < 16; k++) {
            float k0 = sWs[w * 64 + H0i * 16 + k];
            float k1 = sWs[w * 64 + H1i * 16 + k];
            float4 we0 = sWe[k * 64 + L];
            float4 we1 = sWe[k * 64 + 32 + L];
            acc0.x = fmaf(k0, we0.x, acc0.x); acc0.y = fmaf(k0, we0.y, acc0.y);
            acc0.z = fmaf(k0, we0.z, acc0.z); acc0.w = fmaf(k0, we0.w, acc0.w);
            acc1.x = fmaf(k1, we1.x, acc1.x); acc1.y = fmaf(k1, we1.y, acc1.y);
            acc1.z = fmaf(k1, we1.z, acc1.z); acc1.w = fmaf(k1, we1.w, acc1.w);
        }
        float4 sm4;
        sm4.x = acc0.x + acc1.x; sm4.y = acc0.y + acc1.y;
        sm4.z = acc0.z + acc1.z; sm4.w = acc0.w + acc1.w;
        sm4.x += __shfl_xor_sync(0xffffffffu, sm4.x, 16);
        sm4.y += __shfl_xor_sync(0xffffffffu, sm4.y, 16);
        sm4.z += __shfl_xor_sync(0xffffffffu, sm4.z, 16);
        sm4.w += __shfl_xor_sync(0xffffffffu, sm4.w, 16);
        if (L < 16) {
            float4 z1v = *(const float4*)&g_z1[(size_t)n * 64 + 4 * L];
            float4 o;
            o.x = z1v.x + 0.25f * sm4.x;
            o.y = z1v.y + 0.25f * sm4.y;
            o.z = z1v.z + 0.25f * sm4.z;
            o.w = z1v.w + 0.25f * sm4.w;
            *(float4*)&zout[(size_t)n * 64 + 4 * L] = o;
        }
        __syncwarp();
    }
}

// ---------------- decoder: persistent wmma tf32 GEMM ----------------
__global__ void __launch_bounds__(256) k_dec(const int* __restrict__ eli, const float* __restrict__ z,
                                             const float* __restrict__ W1, const float* __restrict__ b1,
                                             const float* __restrict__ W2, const float* __restrict__ b2,
                                             float* __restrict__ pred) {
    extern __shared__ float sm[];
    float* sA = sm;                 // 64*136 (zz rows, later C)
    float* sB = sA + 64 * 136;      // 128*64 W1
    int*   sR = (int*)(sB + 8192);  // 64
    int*   sC = sR + 64;            // 64
    float* sb1 = (float*)(sC + 64); // 64
    float* sw2 = sb1 + 64;          // 64

    int tid = threadIdx.x, L = tid & 31, w = tid >> 5;
    if (tid < 64) { sb1[tid] = b1[tid]; sw2[tid] = W2[tid]; }
    for (int i = tid; i < 2048; i += 256)
        *(float4*)&sB[i * 4] = *(const float4*)&W1[(size_t)i * 4];

    float bb = __ldg(&b2[0]);
    const int rt = w >> 1;          // row-tile 0..3 (16 rows each)
    const int ch = w & 1;           // col half (32 cols)

    const int NT = ELN / 64;
    for (int tile = blockIdx.x; tile < NT; tile += gridDim.x) {
        int ebase = tile * 64;
        __syncthreads();
        if (tid < 64) sR[tid] = __ldg(&eli[ebase + tid]);
        else if (tid < 128) sC[tid - 64] = __ldg(&eli[ELN + ebase + tid - 64]);
        __syncthreads();
        for (int i = tid; i < 2048; i += 256) {
            int e = i >> 5, sg = i & 31;
            int node = (sg < 16) ? sR[e] : sC[e];
            float4 v = *(const float4*)&z[(size_t)node * 64 + (sg & 15) * 4];
            *(float4*)&sA[e * 136 + sg * 4] = v;
        }
        __syncthreads();

        wmma::fragment<wmma::accumulator, 16, 16, 8, float> fc[2];
        wmma::fill_fragment(fc[0], 0.f);
        wmma::fill_fragment(fc[1], 0.f);
        for (int k0 = 0; k0 < 128; k0 += 8) {
            wmma::fragment<wmma::matrix_a, 16, 16, 8, wmma::precision::tf32, wmma::row_major> fa;
            wmma::load_matrix_sync(fa, &sA[rt * 16 * 136 + k0], 136);
#pragma unroll
            for (int i = 0; i < fa.num_elements; i++) fa.x[i] = wmma::__float_to_tf32(fa.x[i]);
#pragma unroll
            for (int cc = 0; cc < 2; cc++) {
                wmma::fragment<wmma::matrix_b, 16, 16, 8, wmma::precision::tf32, wmma::row_major> fb;
                wmma::load_matrix_sync(fb, &sB[k0 * 64 + (ch * 2 + cc) * 16], 64);
#pragma unroll
                for (int i = 0; i < fb.num_elements; i++) fb.x[i] = wmma::__float_to_tf32(fb.x[i]);
                wmma::mma_sync(fc[cc], fa, fb, fc[cc]);
            }
        }
        __syncthreads();   // all fa reads of sA complete before overwrite
#pragma unroll
        for (int cc = 0; cc < 2; cc++)
            wmma::store_matrix_sync(&sA[rt * 16 * 136 + (ch * 2 + cc) * 16], fc[cc], 136, wmma::mem_row_major);
        __syncthreads();

        // epilogue: warp w -> edges w*8 .. w*8+7
        for (int r = 0; r < 8; r++) {
            int row = w * 8 + r;
            float hx = fmaxf(sA[row * 136 + L] + sb1[L], 0.f);
            float hy = fmaxf(sA[row * 136 + 32 + L] + sb1[32 + L], 0.f);
            float p = hx * sw2[L] + hy * sw2[32 + L];
#pragma unroll
            for (int o = 16; o >= 1; o >>= 1) p += __shfl_xor_sync(0xffffffffu, p, o);
            if (L == 0) pred[ebase + row] = p + bb;
        }
    }
}

// ---------------- launch ----------------
extern "C" void kernel_launch(void* const* d_in, const int* in_sizes, int n_in,
                              void* d_out, int out_size) {
    const float* x     = (const float*)d_in[0];
    const int*   ei    = (const int*)d_in[1];
    const int*   ntype = (const int*)d_in[2];
    const float* eattr = (const float*)d_in[3];
    const int*   etype = (const int*)d_in[4];
    const int*   eli   = (const int*)d_in[5];
    const float* Wx1   = (const float*)d_in[6];
    const float* We1   = (const float*)d_in[7];
    const float* nt1   = (const float*)d_in[8];
    const float* et1   = (const float*)d_in[9];
    const float* as1   = (const float*)d_in[10];
    const float* ad1   = (const float*)d_in[11];
    const float* ae1   = (const float*)d_in[12];
    const float* res1  = (const float*)d_in[13];
    const float* Wx2   = (const float*)d_in[14];
    const float* We2   = (const float*)d_in[15];
    const float* nt2   = (const float*)d_in[16];
    const float* et2   = (const float*)d_in[17];
    const float* as2   = (const float*)d_in[18];
    const float* ad2   = (const float*)d_in[19];
    const float* ae2   = (const float*)d_in[20];
    const float* W1    = (const float*)d_in[21];
    const float* b1    = (const float*)d_in[22];
    const float* W2    = (const float*)d_in[23];
    const float* b2    = (const float*)d_in[24];

    float* pred = (float*)d_out;
    float* zout = pred + ELN;

    static bool attr_done = false;
    if (!attr_done) {
        size_t smP2 = (size_t)(128 * 72 + 64 * 64 + 512 + 64 + 64 + 128) * sizeof(float);
        cudaFuncSetAttribute((const void*)k_proj2, cudaFuncAttributeMaxDynamicSharedMemorySize, (int)smP2);
        size_t smD = (size_t)(64 * 136 + 128 * 64 + 64 + 64 + 64 + 64) * sizeof(float);
        cudaFuncSetAttribute((const void*)k_dec, cudaFuncAttributeMaxDynamicSharedMemorySize, (int)smD);
        attr_done = true;
    }
    size_t smP2 = (size_t)(128 * 72 + 64 * 64 + 512 + 64 + 64 + 128) * sizeof(float);
    size_t smD  = (size_t)(64 * 136 + 128 * 64 + 64 + 64 + 64 + 64) * sizeof(float);

    // CSR build
    k_count<<<(EE + 255) / 256, 256>>>(ei);
    k_scanfuse<<<1, 1024>>>(We1, ae1, et1, We2, ae2, et2);
    k_fill<<<(EE + 255) / 256, 256>>>(ei, etype);

    // layer 1 (proj1 is 4th launch -> profiled slot)
    k_proj1<<<592, 256>>>(x, ntype, nt1, Wx1, as1, ad1);
    k_score<1><<<(EE + 255) / 256, 256>>>(ei, eattr, etype);
    k_agg1<<<1184, 256>>>(eattr, We1, et1, x, res1);

    // layer 2
    k_proj2<<<dim3((NN + 127) / 128, 4), 256, smP2>>>(ntype, nt2, Wx2, as2, ad2);
    k_score<2><<<(EE + 255) / 256, 256>>>(ei, eattr, etype);
    k_agg2<<<1184, 256>>>(eattr, We2, et2, zout);

    // decoder
    k_dec<<<592, 256, smD>>>(eli, zout, W1, b1, W2, b2, pred);
}